// round 1
// baseline (speedup 1.0000x reference)
#include <cuda_runtime.h>
#include <cuda_bf16.h>
#include <math.h>

// ---------------- constants ----------------
#define L 256       // tokens
#define C 384       // channels
#define NH 12
#define HD 32
#define NWIN 4
#define MLPD 1536
#define NB 12
#define INV_S 0.99999500003749968f   // 1/sqrt(1+1e-5)

// ---------------- scratch (device globals; no allocs allowed) ----------------
__device__ float g_t[L * C];            // token buffer (residual stream)
__device__ float g_y[L * C];            // LN1 + shift + window order
__device__ float g_qkv[L * 3 * C];      // qkv, window order
__device__ float g_att[L * C];          // attention out, window order
__device__ float g_z[L * C];            // LN2 out
__device__ float g_h1[L * MLPD];        // fc1+gelu out
__device__ float g_part[L * MLPD * 4];  // split-K partials (max 1,572,864 floats)
__device__ float g_col[L * 768];        // im2col for patch embed
__device__ float g_d1[3 * 256 * 256];   // decoder stage-1
__device__ float g_skip[4 * 16 * 16];   // skip features

// ---------------- split-K GEMM: C_part = A(M,K) @ B(N,K)^T ----------------
// BM=BN=64, BK=16, 256 threads, 4x4 microtile. grid=(N/64, M/64, S), Ks=K/S.
__global__ __launch_bounds__(256) void gemm_sk(
    const float* __restrict__ A, const float* __restrict__ B,
    float* __restrict__ part, int M, int N, int K, int Ks)
{
    __shared__ float As[16][68];
    __shared__ float Bs[16][68];
    int bn = blockIdx.x * 64;
    int bm = blockIdx.y * 64;
    int k0 = blockIdx.z * Ks;
    int tid = threadIdx.x;
    int tx = tid & 15, ty = tid >> 4;
    int lr = tid >> 2;            // 0..63 row within tile
    int lc = (tid & 3) * 4;       // 0,4,8,12 k-offset
    float acc[4][4];
#pragma unroll
    for (int i = 0; i < 4; i++)
#pragma unroll
        for (int j = 0; j < 4; j++) acc[i][j] = 0.f;

    for (int kt = 0; kt < Ks; kt += 16) {
        float4 av = *(const float4*)(A + (size_t)(bm + lr) * K + k0 + kt + lc);
        float4 bv = *(const float4*)(B + (size_t)(bn + lr) * K + k0 + kt + lc);
        As[lc + 0][lr] = av.x; As[lc + 1][lr] = av.y; As[lc + 2][lr] = av.z; As[lc + 3][lr] = av.w;
        Bs[lc + 0][lr] = bv.x; Bs[lc + 1][lr] = bv.y; Bs[lc + 2][lr] = bv.z; Bs[lc + 3][lr] = bv.w;
        __syncthreads();
#pragma unroll
        for (int kk = 0; kk < 16; kk++) {
            float4 a = *(const float4*)&As[kk][ty * 4];
            float4 b = *(const float4*)&Bs[kk][tx * 4];
            acc[0][0] += a.x * b.x; acc[0][1] += a.x * b.y; acc[0][2] += a.x * b.z; acc[0][3] += a.x * b.w;
            acc[1][0] += a.y * b.x; acc[1][1] += a.y * b.y; acc[1][2] += a.y * b.z; acc[1][3] += a.y * b.w;
            acc[2][0] += a.z * b.x; acc[2][1] += a.z * b.y; acc[2][2] += a.z * b.z; acc[2][3] += a.z * b.w;
            acc[3][0] += a.w * b.x; acc[3][1] += a.w * b.y; acc[3][2] += a.w * b.z; acc[3][3] += a.w * b.w;
        }
        __syncthreads();
    }
    float* P = part + (size_t)blockIdx.z * M * N;
#pragma unroll
    for (int i = 0; i < 4; i++)
#pragma unroll
        for (int j = 0; j < 4; j++)
            P[(size_t)(bm + ty * 4 + i) * N + bn + tx * 4 + j] = acc[i][j];
}

// ---------------- epilogues (sum split-K partials + fused ops) ----------------
__global__ void epi_plain(const float* __restrict__ part, float* __restrict__ out, int MN, int S)
{
    int i = blockIdx.x * 256 + threadIdx.x;
    if (i >= MN) return;
    float s = 0.f;
    for (int z = 0; z < S; z++) s += part[(size_t)z * MN + i];
    out[i] = s;
}

__global__ void epi_patch(const float* __restrict__ part, const float* __restrict__ pb,
                          const float* __restrict__ pos, float* __restrict__ t, int S)
{
    const int MN = L * C;
    int i = blockIdx.x * 256 + threadIdx.x;
    if (i >= MN) return;
    int m = i / C, n = i % C;   // m = patch, n = out-channel
    float s = 0.f;
    for (int z = 0; z < S; z++) s += part[(size_t)z * MN + i];
    int o = n * 256 + m;        // buggy-flatten linear index
    t[o] = s + pb[n] + pos[o];
}

__global__ void epi_proj(const float* __restrict__ part, const float* __restrict__ pb,
                         float* __restrict__ t, int S)
{
    const int MN = L * C;
    int i = blockIdx.x * 256 + threadIdx.x;
    if (i >= MN) return;
    int m = i / C, n = i % C;
    float s = pb[n];
    for (int z = 0; z < S; z++) s += part[(size_t)z * MN + i];
    // window row -> spatial (shifted) -> unshift
    int wi = m >> 6, pos = m & 63;
    int hs = ((wi >> 1) << 3) + (pos >> 3);
    int ws = ((wi & 1) << 3) + (pos & 7);
    int h = (hs + 4) & 15, w = (ws + 4) & 15;
    t[(h * 16 + w) * C + n] += s;
}

__global__ void epi_gelu(const float* __restrict__ part, const float* __restrict__ b1,
                         float* __restrict__ h1, int S)
{
    const int MN = L * MLPD;
    int i = blockIdx.x * 256 + threadIdx.x;
    if (i >= MN) return;
    int n = i % MLPD;
    float s = b1[n];
    for (int z = 0; z < S; z++) s += part[(size_t)z * MN + i];
    h1[i] = 0.5f * s * (1.0f + erff(s * 0.70710678118654752f));
}

__global__ void epi_res(const float* __restrict__ part, const float* __restrict__ b2,
                        float* __restrict__ t, int S)
{
    const int MN = L * C;
    int i = blockIdx.x * 256 + threadIdx.x;
    if (i >= MN) return;
    int n = i % C;
    float s = b2[n];
    for (int z = 0; z < S; z++) s += part[(size_t)z * MN + i];
    t[i] += s;
}

// ---------------- LayerNorm (optionally fused shift + window partition) ----------------
template <bool SW>
__global__ void ln_kernel(const float* __restrict__ t, const float* __restrict__ w,
                          const float* __restrict__ bb, float* __restrict__ y)
{
    int hw = blockIdx.x;
    int tid = threadIdx.x;   // 128 threads, 3 elems each
    int srcRow, dstRow;
    if (SW) {
        int h = hw >> 4, wd = hw & 15;
        srcRow = (((h + 4) & 15) << 4) + ((wd + 4) & 15);
        int wi = ((h >> 3) << 1) + (wd >> 3);
        int pos = ((h & 7) << 3) + (wd & 7);
        dstRow = wi * 64 + pos;
    } else {
        srcRow = hw; dstRow = hw;
    }
    const float* src = t + srcRow * C;
    float x0 = src[tid], x1 = src[tid + 128], x2 = src[tid + 256];
    __shared__ float red[4];
    float s = x0 + x1 + x2;
#pragma unroll
    for (int o = 16; o; o >>= 1) s += __shfl_xor_sync(0xffffffffu, s, o);
    if ((tid & 31) == 0) red[tid >> 5] = s;
    __syncthreads();
    float mean = (red[0] + red[1] + red[2] + red[3]) * (1.0f / 384.0f);
    float d0 = x0 - mean, d1 = x1 - mean, d2 = x2 - mean;
    float s2 = d0 * d0 + d1 * d1 + d2 * d2;
#pragma unroll
    for (int o = 16; o; o >>= 1) s2 += __shfl_xor_sync(0xffffffffu, s2, o);
    __syncthreads();
    if ((tid & 31) == 0) red[tid >> 5] = s2;
    __syncthreads();
    float var = (red[0] + red[1] + red[2] + red[3]) * (1.0f / 384.0f);
    float rstd = rsqrtf(var + 1e-5f);
    float* dst = y + dstRow * C;
    dst[tid]       = d0 * rstd * w[tid]       + bb[tid];
    dst[tid + 128] = d1 * rstd * w[tid + 128] + bb[tid + 128];
    dst[tid + 256] = d2 * rstd * w[tid + 256] + bb[tid + 256];
}

// ---------------- windowed attention ----------------
__device__ __forceinline__ int region3(int h) { return h < 8 ? 0 : (h < 12 ? 1 : 2); }

__global__ void attn_kernel(const float* __restrict__ qkv, const float* __restrict__ rpb,
                            float* __restrict__ att)
{
    int wi = blockIdx.x / NH;
    int hd = blockIdx.x % NH;
    __shared__ float ks[64][32];
    __shared__ float vs[64][32];
    int tid = threadIdx.x;   // 64 threads, thread = query row
    const float* base = qkv + (size_t)wi * 64 * (3 * C) + hd * HD;
    float q[32];
#pragma unroll
    for (int d4 = 0; d4 < 8; d4++) {
        float4 kv = *(const float4*)(base + (size_t)tid * (3 * C) + C + d4 * 4);
        *(float4*)&ks[tid][d4 * 4] = kv;
        float4 vv = *(const float4*)(base + (size_t)tid * (3 * C) + 2 * C + d4 * 4);
        *(float4*)&vs[tid][d4 * 4] = vv;
        float4 qv = *(const float4*)(base + (size_t)tid * (3 * C) + d4 * 4);
        q[d4 * 4 + 0] = qv.x; q[d4 * 4 + 1] = qv.y; q[d4 * 4 + 2] = qv.z; q[d4 * 4 + 3] = qv.w;
    }
    __syncthreads();

    int i = tid;
    int yi = i >> 3, xi = i & 7;
    int ri = region3(((wi >> 1) << 3) + yi) * 3 + region3(((wi & 1) << 3) + xi);
    const float scale = 0.17677669529663687f;
    float s[64];
#pragma unroll 4
    for (int j = 0; j < 64; j++) {
        float acc = 0.f;
#pragma unroll
        for (int d = 0; d < 32; d++) acc += q[d] * ks[j][d];
        int yj = j >> 3, xj = j & 7;
        int rel = (yi - yj + 7) * 15 + (xi - xj + 7);
        float bias = rpb[rel * NH + hd];
        int rj = region3(((wi >> 1) << 3) + yj) * 3 + region3(((wi & 1) << 3) + xj);
        float mask = (ri == rj) ? 0.f : -100.f;
        s[j] = acc * scale + bias + mask;
    }
    float mx = -1e30f;
#pragma unroll
    for (int j = 0; j < 64; j++) mx = fmaxf(mx, s[j]);
    float sum = 0.f;
#pragma unroll
    for (int j = 0; j < 64; j++) { s[j] = expf(s[j] - mx); sum += s[j]; }
    float inv = 1.0f / sum;
    float* o = att + (size_t)(wi * 64 + i) * C + hd * HD;
#pragma unroll
    for (int d = 0; d < 32; d++) {
        float acc = 0.f;
#pragma unroll 8
        for (int j = 0; j < 64; j++) acc += s[j] * vs[j][d];
        o[d] = acc * inv;
    }
}

// ---------------- patch embed im2col ----------------
__global__ void im2col_kernel(const float* __restrict__ x, float* __restrict__ col)
{
    int i = blockIdx.x * 256 + threadIdx.x;   // < 256*768
    if (i >= 256 * 768) return;
    int patch = i / 768, r = i % 768;
    int c = r >> 8, pq = r & 255, p = pq >> 4, q = pq & 15;
    int h = patch >> 4, w = patch & 15;
    col[i] = x[c * 65536 + (h * 16 + p) * 256 + (w * 16 + q)];
}

// ---------------- decoder: skip 1x1 conv ----------------
__global__ void skip_kernel(const float* __restrict__ t, const float* __restrict__ sw,
                            const float* __restrict__ sb, float* __restrict__ skip)
{
    int i = blockIdx.x * 256 + threadIdx.x;   // < 1024
    if (i >= 1024) return;
    int o = i >> 8, hw = i & 255;
    float acc = sb[o];
    for (int c = 0; c < C; c++) acc += t[hw * C + c] * sw[o * C + c];
    skip[i] = acc;
}

// ---------------- decoder stage 1: deconv(C->3, k16 s16) + BN + ReLU ----------------
__global__ __launch_bounds__(768) void d1_kernel(
    const float* __restrict__ t, const float* __restrict__ w1, const float* __restrict__ b1,
    const float* __restrict__ bnw, const float* __restrict__ bnb, float* __restrict__ d1)
{
    __shared__ float ts[8][384];
    int tid = threadIdx.x;               // 768 = 3 * 256
    int p0 = blockIdx.x * 8;             // 32 blocks x 8 patches
#pragma unroll
    for (int v = 0; v < 4; v++) {
        int idx = v * 768 + tid;
        ts[idx / 384][idx % 384] = t[(p0 + idx / 384) * C + (idx % 384)];
    }
    __syncthreads();
    int o = tid >> 8;
    float acc[8];
#pragma unroll
    for (int g = 0; g < 8; g++) acc[g] = b1[o];
    for (int c = 0; c < C; c++) {
        float wv = w1[c * 768 + tid];
#pragma unroll
        for (int g = 0; g < 8; g++) acc[g] += ts[g][c] * wv;
    }
    float a = bnw[o] * INV_S, bbv = bnb[o];
    int k = (tid >> 4) & 15, l = tid & 15;
#pragma unroll
    for (int g = 0; g < 8; g++) {
        int patch = p0 + g;
        int h = patch >> 4, w = patch & 15;
        d1[o * 65536 + (h * 16 + k) * 256 + (w * 16 + l)] = fmaxf(0.f, acc[g] * a + bbv);
    }
}

// ---------------- decoder final: deconv(3->4, k16 s16) + BN + bilinear skip + reshape ----------------
__global__ void final_kernel(const float* __restrict__ d1, const float* __restrict__ w2,
                             const float* __restrict__ b2, const float* __restrict__ bnw,
                             const float* __restrict__ bnb, const float* __restrict__ skip,
                             float* __restrict__ out)
{
    int idx = blockIdx.x * 256 + threadIdx.x;   // < 4*4096*4096 = 67,108,864
    int o = idx >> 24;
    int rem = idx & 0xFFFFFF;
    int Y = rem >> 12, X = rem & 4095;
    int H = Y >> 4, k = Y & 15, W = X >> 4, l = X & 15;
    int kl = k * 16 + l;
    float acc = b2[o];
#pragma unroll
    for (int c = 0; c < 3; c++)
        acc += d1[c * 65536 + H * 256 + W] * w2[c * 1024 + o * 256 + kl];
    acc = acc * INV_S * bnw[o] + bnb[o];
    // bilinear align_corners 16 -> 4096 : s = Y*15/4095 = Y/273 exactly
    int y0 = Y / 273, x0 = X / 273;
    float fy = (float)(Y - y0 * 273) * (1.0f / 273.0f);
    float fx = (float)(X - x0 * 273) * (1.0f / 273.0f);
    int y1 = min(y0 + 1, 15), x1 = min(x0 + 1, 15);
    const float* sk = skip + o * 256;
    float v00 = sk[y0 * 16 + x0], v01 = sk[y0 * 16 + x1];
    float v10 = sk[y1 * 16 + x0], v11 = sk[y1 * 16 + x1];
    float vt = v00 + (v01 - v00) * fx;
    float vb = v10 + (v11 - v10) * fx;
    out[idx] = acc + vt + (vb - vt) * fy;
}

// ---------------- host launch ----------------
extern "C" void kernel_launch(void* const* d_in, const int* in_sizes, int n_in,
                              void* d_out, int out_size)
{
    const float* x       = (const float*)d_in[0];
    const float* patch_w = (const float*)d_in[1];
    const float* patch_b = (const float*)d_in[2];
    const float* pos     = (const float*)d_in[3];
    const float* ln1_w   = (const float*)d_in[4];
    const float* ln1_b   = (const float*)d_in[5];
    const float* qkv_w   = (const float*)d_in[6];
    const float* proj_w  = (const float*)d_in[7];
    const float* proj_b  = (const float*)d_in[8];
    const float* rpb     = (const float*)d_in[9];
    const float* ln2_w   = (const float*)d_in[10];
    const float* ln2_b   = (const float*)d_in[11];
    const float* fc1_w   = (const float*)d_in[12];
    const float* fc1_b   = (const float*)d_in[13];
    const float* fc2_w   = (const float*)d_in[14];
    const float* fc2_b   = (const float*)d_in[15];
    const float* skip_w  = (const float*)d_in[16];
    const float* skip_b  = (const float*)d_in[17];
    const float* dt1_w   = (const float*)d_in[18];
    const float* dt1_b   = (const float*)d_in[19];
    const float* bn1_w   = (const float*)d_in[20];
    const float* bn1_b   = (const float*)d_in[21];
    const float* dt2_w   = (const float*)d_in[22];
    const float* dt2_b   = (const float*)d_in[23];
    const float* bn2_w   = (const float*)d_in[24];
    const float* bn2_b   = (const float*)d_in[25];
    float* out = (float*)d_out;

    float *t, *y, *qkv, *att, *z, *h1, *part, *col, *d1, *skip;
    cudaGetSymbolAddress((void**)&t,    g_t);
    cudaGetSymbolAddress((void**)&y,    g_y);
    cudaGetSymbolAddress((void**)&qkv,  g_qkv);
    cudaGetSymbolAddress((void**)&att,  g_att);
    cudaGetSymbolAddress((void**)&z,    g_z);
    cudaGetSymbolAddress((void**)&h1,   g_h1);
    cudaGetSymbolAddress((void**)&part, g_part);
    cudaGetSymbolAddress((void**)&col,  g_col);
    cudaGetSymbolAddress((void**)&d1,   g_d1);
    cudaGetSymbolAddress((void**)&skip, g_skip);

    // ---- patch embed: im2col + GEMM(M=256,N=384,K=768,S=4) -> t (+pos, transposed) ----
    im2col_kernel<<<768, 256>>>(x, col);
    gemm_sk<<<dim3(6, 4, 4), 256>>>(col, patch_w, part, 256, 384, 768, 192);
    epi_patch<<<384, 256>>>(part, patch_b, pos, t, 4);

    // ---- 12 transformer blocks ----
    for (int b = 0; b < NB; b++) {
        ln_kernel<true><<<256, 128>>>(t, ln1_w + b * C, ln1_b + b * C, y);
        // qkv: M=256, N=1152, K=384, S=4
        gemm_sk<<<dim3(18, 4, 4), 256>>>(y, qkv_w + (size_t)b * 3 * C * C, part, 256, 1152, 384, 96);
        epi_plain<<<1152, 256>>>(part, qkv, 256 * 1152, 4);
        attn_kernel<<<48, 64>>>(qkv, rpb + (size_t)b * 225 * NH, att);
        // proj: M=256, N=384, K=384, S=8
        gemm_sk<<<dim3(6, 4, 8), 256>>>(att, proj_w + (size_t)b * C * C, part, 256, 384, 384, 48);
        epi_proj<<<384, 256>>>(part, proj_b + b * C, t, 8);
        ln_kernel<false><<<256, 128>>>(t, ln2_w + b * C, ln2_b + b * C, z);
        // fc1: M=256, N=1536, K=384, S=4
        gemm_sk<<<dim3(24, 4, 4), 256>>>(z, fc1_w + (size_t)b * MLPD * C, part, 256, 1536, 384, 96);
        epi_gelu<<<1536, 256>>>(part, fc1_b + b * MLPD, h1, 4);
        // fc2: M=256, N=384, K=1536, S=8
        gemm_sk<<<dim3(6, 4, 8), 256>>>(h1, fc2_w + (size_t)b * C * MLPD, part, 256, 384, 1536, 192);
        epi_res<<<384, 256>>>(part, fc2_b + b * C, t, 8);
    }

    // ---- decoder ----
    skip_kernel<<<4, 256>>>(t, skip_w, skip_b, skip);
    d1_kernel<<<32, 768>>>(t, dt1_w, dt1_b, bn1_w, bn1_b, d1);
    final_kernel<<<262144, 256>>>(d1, dt2_w, dt2_b, bn2_w, bn2_b, skip, out);
}